// round 8
// baseline (speedup 1.0000x reference)
#include <cuda_runtime.h>
#include <cuda_bf16.h>

// pred, true: [B=2, C=16, D=64, H=128, W=128] f32 ; weight: [16] f32 ; out: scalar f32
// result = ( sum_i w[class(i)] * bce_i ) / (sum_w * B*D*H*W)
// Layout [B,C,D,H,W]: f4-index i belongs to class ((i >> 18) & 15)
// (SPATIAL/4 = 262,144 = 2^18 float4 per (b,c) segment).
//
// Balanced persistent grid: 148 SMs x 8 CTAs, global grid-stride so all CTAs
// march through memory in lockstep (minimal finish-time spread / tail).
// Single-kernel ticket reduction; counter reset for graph-replay safety.
//
// Math in log2 domain: bce/ln2 = -(t*(lg2 p - lg2 q) + lg2 q), q=1-p.
// Clamp at -100/ln2. ln2 folded into the per-block double partial.

#define TOTAL_F4   (2u * 16u * 64u * 128u * 128u / 4u)  // 8,388,608
#define SEG_SHIFT  18                                   // log2(SPATIAL/4)
#define C_CLASSES  16
#define NBLOCKS    (148 * 8)                            // 1184
#define THREADS    256
#define STRIDE     ((unsigned)NBLOCKS * THREADS)        // 303,104

#define LN2      0.6931471805599453
#define CLAMP_L2 (-144.269504f)   // -100 / ln2

__device__ double       g_partials[NBLOCKS];
__device__ unsigned int g_count = 0;

__device__ __forceinline__ float bce_l2(float p, float t) {
    float a = fmaxf(__log2f(p), CLAMP_L2);
    float b = fmaxf(__log2f(1.0f - p), CLAMP_L2);
    return -fmaf(t, a - b, b);            // bce / ln2
}

__device__ __forceinline__ float bce4_l2(float4 p, float4 t) {
    return bce_l2(p.x, t.x) + bce_l2(p.y, t.y)
         + bce_l2(p.z, t.z) + bce_l2(p.w, t.w);
}

__global__ __launch_bounds__(THREADS)
void bce_reduce_kernel(const float4* __restrict__ pred,
                       const float4* __restrict__ tru,
                       const float*  __restrict__ weight,
                       float* __restrict__ out) {
    __shared__ float s_w[C_CLASSES];
    if (threadIdx.x < C_CLASSES) s_w[threadIdx.x] = __ldg(&weight[threadIdx.x]);
    __syncthreads();

    float acc = 0.0f;
    unsigned i = blockIdx.x * THREADS + threadIdx.x;

    #pragma unroll 4
    for (; i < TOTAL_F4; i += STRIDE) {
        float4 p = __ldcg(&pred[i]);
        float4 t = __ldcg(&tru [i]);
        const float wv = s_w[(i >> SEG_SHIFT) & (C_CLASSES - 1)];  // warp-uniform
        acc = fmaf(wv, bce4_l2(p, t), acc);
    }

    // warp reduce
    #pragma unroll
    for (int off = 16; off > 0; off >>= 1)
        acc += __shfl_xor_sync(0xFFFFFFFFu, acc, off);

    __shared__ float warp_sums[THREADS / 32];
    const int lane = threadIdx.x & 31;
    const int wid  = threadIdx.x >> 5;
    if (lane == 0) warp_sums[wid] = acc;
    __syncthreads();

    __shared__ bool is_last;
    if (threadIdx.x == 0) {
        float v = 0.0f;
        #pragma unroll
        for (int w = 0; w < THREADS / 32; w++) v += warp_sums[w];
        g_partials[blockIdx.x] = (double)v * LN2;   // log2 -> ln
        __threadfence();
        unsigned int ticket = atomicAdd(&g_count, 1u);
        is_last = (ticket == NBLOCKS - 1);
    }
    __syncthreads();

    if (is_last) {
        double d = 0.0;
        for (int k = threadIdx.x; k < NBLOCKS; k += THREADS)
            d += g_partials[k];

        #pragma unroll
        for (int off = 16; off > 0; off >>= 1)
            d += __shfl_xor_sync(0xFFFFFFFFu, d, off);

        __shared__ double dwarp[THREADS / 32];
        if (lane == 0) dwarp[wid] = d;
        __syncthreads();

        if (threadIdx.x == 0) {
            double total = 0.0;
            #pragma unroll
            for (int w = 0; w < THREADS / 32; w++) total += dwarp[w];
            double sum_w = 0.0;
            #pragma unroll
            for (int c = 0; c < C_CLASSES; c++) sum_w += (double)__ldg(&weight[c]);
            const double denom = sum_w * (double)(2.0 * 64.0 * 128.0 * 128.0);
            out[0] = (float)(total / denom);
            g_count = 0;   // reset for next graph replay
        }
    }
}

extern "C" void kernel_launch(void* const* d_in, const int* in_sizes, int n_in,
                              void* d_out, int out_size) {
    const float4* pred = (const float4*)d_in[0];
    const float4* tru  = (const float4*)d_in[1];
    const float*  w    = (const float*)d_in[2];
    bce_reduce_kernel<<<NBLOCKS, THREADS>>>(pred, tru, w, (float*)d_out);
}

// round 9
// speedup vs baseline: 1.1053x; 1.1053x over previous
#include <cuda_runtime.h>
#include <cuda_bf16.h>

// pred, true: [B=2, C=16, D=64, H=128, W=128] f32 ; weight: [16] f32 ; out: scalar f32
// result = ( sum_i w[class(i)] * bce_i ) / (sum_w * B*D*H*W)
// Layout [B,C,D,H,W]: each contiguous SPATIAL=1,048,576-element segment is one
// class (seg % 16). Weight hoisted once per block.
//
// Grid = 32 segments x 37 blocks = 1184 = 148 SMs x 8 CTAs: exactly one wave,
// every SM equally loaded. __launch_bounds__(256,8) pins regs <= 32 so all
// 8 CTAs are simultaneously resident (R6 lesson: 36 regs -> 7/SM -> tail wave).
//
// Math in log2 domain: bce/ln2 = -(t*(lg2 p - lg2 q) + lg2 q), q=1-p.
// Clamp at -100/ln2. ln2 folded into the per-block double partial.

#define F4_PER_SEG     (1048576 / 4)       // 262,144 float4 per (b,c) segment
#define N_SEGS         32                  // B*C
#define C_CLASSES      16
#define BLOCKS_PER_SEG 37
#define NBLOCKS        (N_SEGS * BLOCKS_PER_SEG)   // 1184 = 148*8
#define THREADS        256
#define CHUNK          7086                // ceil(262144/37); last block short

#define LN2      0.6931471805599453
#define CLAMP_L2 (-144.269504f)   // -100 / ln2

__device__ double       g_partials[NBLOCKS];
__device__ unsigned int g_count = 0;

__device__ __forceinline__ float bce_l2(float p, float t) {
    float a = fmaxf(__log2f(p), CLAMP_L2);
    float b = fmaxf(__log2f(1.0f - p), CLAMP_L2);
    return -fmaf(t, a - b, b);            // bce / ln2
}

__device__ __forceinline__ float bce4_l2(float4 p, float4 t) {
    return bce_l2(p.x, t.x) + bce_l2(p.y, t.y)
         + bce_l2(p.z, t.z) + bce_l2(p.w, t.w);
}

__global__ __launch_bounds__(THREADS, 8)
void bce_reduce_kernel(const float4* __restrict__ pred,
                       const float4* __restrict__ tru,
                       const float*  __restrict__ weight,
                       float* __restrict__ out) {
    const int seg = blockIdx.x / BLOCKS_PER_SEG;
    const int sub = blockIdx.x % BLOCKS_PER_SEG;
    const int start = sub * CHUNK;
    const int end   = (start + CHUNK < F4_PER_SEG) ? (start + CHUNK) : F4_PER_SEG;
    const float4* __restrict__ ps = pred + (size_t)seg * F4_PER_SEG;
    const float4* __restrict__ ts = tru  + (size_t)seg * F4_PER_SEG;

    float acc = 0.0f;
    #pragma unroll 4
    for (int i = start + threadIdx.x; i < end; i += THREADS) {
        float4 p = __ldg(&ps[i]);
        float4 t = __ldg(&ts[i]);
        acc += bce4_l2(p, t);
    }

    // warp reduce
    #pragma unroll
    for (int off = 16; off > 0; off >>= 1)
        acc += __shfl_xor_sync(0xFFFFFFFFu, acc, off);

    __shared__ float warp_sums[THREADS / 32];
    const int lane = threadIdx.x & 31;
    const int wid  = threadIdx.x >> 5;
    if (lane == 0) warp_sums[wid] = acc;
    __syncthreads();

    __shared__ bool is_last;
    if (threadIdx.x == 0) {
        float v = 0.0f;
        #pragma unroll
        for (int w = 0; w < THREADS / 32; w++) v += warp_sums[w];
        const float wc = __ldg(&weight[seg & (C_CLASSES - 1)]);
        g_partials[blockIdx.x] = (double)v * (double)wc * LN2;
        __threadfence();
        unsigned int ticket = atomicAdd(&g_count, 1u);
        is_last = (ticket == NBLOCKS - 1);
    }
    __syncthreads();

    if (is_last) {
        double d = 0.0;
        for (int k = threadIdx.x; k < NBLOCKS; k += THREADS)
            d += g_partials[k];

        #pragma unroll
        for (int off = 16; off > 0; off >>= 1)
            d += __shfl_xor_sync(0xFFFFFFFFu, d, off);

        __shared__ double dwarp[THREADS / 32];
        if (lane == 0) dwarp[wid] = d;
        __syncthreads();

        if (threadIdx.x == 0) {
            double total = 0.0;
            #pragma unroll
            for (int w = 0; w < THREADS / 32; w++) total += dwarp[w];
            double sum_w = 0.0;
            #pragma unroll
            for (int c = 0; c < C_CLASSES; c++) sum_w += (double)__ldg(&weight[c]);
            const double denom = sum_w * (double)(2.0 * 64.0 * 128.0 * 128.0);
            out[0] = (float)(total / denom);
            g_count = 0;   // reset for next graph replay
        }
    }
}

extern "C" void kernel_launch(void* const* d_in, const int* in_sizes, int n_in,
                              void* d_out, int out_size) {
    const float4* pred = (const float4*)d_in[0];
    const float4* tru  = (const float4*)d_in[1];
    const float*  w    = (const float*)d_in[2];
    bce_reduce_kernel<<<NBLOCKS, THREADS>>>(pred, tru, w, (float*)d_out);
}